// round 14
// baseline (speedup 1.0000x reference)
#include <cuda_runtime.h>
#include <math.h>

#define N2 512
#define DM 256
#define NSPLIT 4
#define KS 64        // k-width per split chunk
#define NT 16        // 16 tiles of 32 per dim; symmetric pairs = 136
#define NBLK 544     // 136 pairs x 4 splits

__device__ float g_gram[NSPLIT][N2 * N2];   // partial Gram sums (4 MB)
__device__ float g_norm[N2];
__device__ float g_ts[N2];
__device__ int   g_perm[N2];
__device__ float g_part[N2];
__device__ volatile unsigned g_sense  = 0;  // barrier 1 release flag
__device__ unsigned g_count  = 0;           // barrier 1 arrivals
__device__ unsigned g_count2 = 0;           // barrier 2 arrivals

union SmemU {
    struct { float At[KS][34]; float Bt[KS][34]; } gemm;    // 17408 B (even stride: float2-safe)
    struct { float drow[N2], ts[N2], ds[N2], sv[N2];
             float psX[N2 + 1], ssX[N2 + 1]; } loss;        // 12296 B
};

__global__ void __launch_bounds__(256, 4) fused_kernel(
    const float* __restrict__ E, const float* __restrict__ T,
    float* __restrict__ out)
{
    __shared__ SmemU sm;
    __shared__ float wtot[8];
    __shared__ float red[8];
    __shared__ int   ri_sh;

    const int bid  = blockIdx.x;
    const int tid  = threadIdx.x;
    const int lane = tid & 31;
    const int w    = tid >> 5;

    // ===== PHASE A: symmetric split-k Gram, 32x32 tiles, single 64-k chunk =====
    // bid -> (pair 0..135 [a<=b over 16 tiles], split 0..3)
    {
        const int pr    = bid >> 2;
        const int split = bid & 3;
        int a = 0, rem = pr, len = NT;
        while (rem >= len) { rem -= len; a++; len--; }
        const int b = a + rem;
        const int kbase = split * KS;

        // loaders: r = row in 32-tile (0..31), cq = k-octet (0..7), 8 floats each
        const int r  = tid >> 3;
        const int cq = tid & 7;
        const float* Ea = E + (a * 32 + r) * DM + kbase + cq * 8;
        const float* Eb = E + (b * 32 + r) * DM + kbase + cq * 8;
        float4 a1 = *reinterpret_cast<const float4*>(Ea);
        float4 a2 = *reinterpret_cast<const float4*>(Ea + 4);
        float4 b1 = *reinterpret_cast<const float4*>(Eb);
        float4 b2 = *reinterpret_cast<const float4*>(Eb + 4);

        const int kb = cq * 8;
        sm.gemm.At[kb + 0][r] = a1.x; sm.gemm.At[kb + 1][r] = a1.y;
        sm.gemm.At[kb + 2][r] = a1.z; sm.gemm.At[kb + 3][r] = a1.w;
        sm.gemm.At[kb + 4][r] = a2.x; sm.gemm.At[kb + 5][r] = a2.y;
        sm.gemm.At[kb + 6][r] = a2.z; sm.gemm.At[kb + 7][r] = a2.w;
        sm.gemm.Bt[kb + 0][r] = b1.x; sm.gemm.Bt[kb + 1][r] = b1.y;
        sm.gemm.Bt[kb + 2][r] = b1.z; sm.gemm.Bt[kb + 3][r] = b1.w;
        sm.gemm.Bt[kb + 4][r] = b2.x; sm.gemm.Bt[kb + 5][r] = b2.y;
        sm.gemm.Bt[kb + 6][r] = b2.z; sm.gemm.Bt[kb + 7][r] = b2.w;
        __syncthreads();

        // compute: 2x2 microtile, 16x16 thread grid
        const int tx = tid & 15, ty = tid >> 4;
        float a00 = 0.f, a01 = 0.f, a10 = 0.f, a11 = 0.f;

        #pragma unroll
        for (int kk = 0; kk < KS; kk++) {
            float2 x = *reinterpret_cast<const float2*>(&sm.gemm.At[kk][2 * ty]);
            float2 y = *reinterpret_cast<const float2*>(&sm.gemm.Bt[kk][2 * tx]);
            a00 = fmaf(x.x, y.x, a00);
            a01 = fmaf(x.x, y.y, a01);
            a10 = fmaf(x.y, y.x, a10);
            a11 = fmaf(x.y, y.y, a11);
        }

        float* G = g_gram[split];
        const int gi = a * 32 + 2 * ty, gj = b * 32 + 2 * tx;
        float2 v;
        v.x = a00; v.y = a01;
        *reinterpret_cast<float2*>(&G[(gi    ) * N2 + gj]) = v;
        v.x = a10; v.y = a11;
        *reinterpret_cast<float2*>(&G[(gi + 1) * N2 + gj]) = v;
        if (a != b) {
            v.x = a00; v.y = a10;
            *reinterpret_cast<float2*>(&G[(gj    ) * N2 + gi]) = v;
            v.x = a01; v.y = a11;
            *reinterpret_cast<float2*>(&G[(gj + 1) * N2 + gi]) = v;
        }
    }

    // ---- rank + norm for element bid (warp 0 of blocks 0..511) ----
    if (w == 0 && bid < N2) {
        const int e = bid;
        const float tv = __ldg(&T[e]);
        int cnt = 0;
        float nrm = 0.0f;
        #pragma unroll
        for (int c = 0; c < 16; c++) {
            int jj = lane + c * 32;
            float o = __ldg(&T[jj]);
            cnt += (o < tv || (o == tv && jj < e)) ? 1 : 0;
            if (c < 8) {
                float v = __ldg(&E[e * DM + jj]);
                nrm = fmaf(v, v, nrm);
            }
        }
        #pragma unroll
        for (int o = 16; o > 0; o >>= 1) {
            cnt += __shfl_xor_sync(0xffffffffu, cnt, o);
            nrm += __shfl_xor_sync(0xffffffffu, nrm, o);
        }
        if (lane == 0) { g_ts[cnt] = tv; g_perm[cnt] = e; g_norm[e] = nrm; }
    }

    // ============ BARRIER 1 (volatile-load spin) ============
    __syncthreads();
    if (tid == 0) {
        __threadfence();
        unsigned a = atomicAdd(&g_count, 1u);
        if (a == NBLK - 1) {
            g_count = 0;
            __threadfence();
            g_sense = 1u;
        } else {
            while (g_sense != 1u) { __nanosleep(64); }
        }
        __threadfence();
    }
    __syncthreads();

    // ============ PHASE B: loss row i = bid (blocks 0..511) ============
    if (bid < N2) {
        const int i = bid;
        const float ni = __ldg(&g_norm[i]);

        {
            float2 gsum = make_float2(0.0f, 0.0f);
            #pragma unroll
            for (int s = 0; s < NSPLIT; s++) {
                float2 gv = *reinterpret_cast<const float2*>(&g_gram[s][i * N2 + 2 * tid]);
                gsum.x += gv.x; gsum.y += gv.y;
            }
            float2 nv = *reinterpret_cast<const float2*>(&g_norm[2 * tid]);
            sm.loss.drow[2 * tid]     = sqrtf(fmaxf(ni + nv.x - 2.0f * gsum.x, 0.0f));
            sm.loss.drow[2 * tid + 1] = sqrtf(fmaxf(ni + nv.y - 2.0f * gsum.y, 0.0f));
            sm.loss.ts[2 * tid]     = g_ts[2 * tid];
            sm.loss.ts[2 * tid + 1] = g_ts[2 * tid + 1];
        }
        __syncthreads();

        const float ti = __ldg(&T[i]);

        #pragma unroll
        for (int c = 0; c < 2; c++) {
            int e = tid + c * 256;
            int p = g_perm[e];
            float d = sm.loss.drow[p];
            sm.loss.ds[e] = d;
            if (p == i) { sm.loss.sv[e] = 1.0f; ri_sh = e; }
            else        { sm.loss.sv[e] = __expf(-d); }
        }
        __syncthreads();

        // dual scan, additions only (thread owns sorted elements 2t, 2t+1)
        const float v0 = sm.loss.sv[2 * tid], v1 = sm.loss.sv[2 * tid + 1];
        const float pairv = v0 + v1;

        float p = pairv;
        #pragma unroll
        for (int off = 1; off < 32; off <<= 1) {
            float tmp = __shfl_up_sync(0xffffffffu, p, off);
            if (lane >= off) p += tmp;
        }
        float q = pairv;
        #pragma unroll
        for (int off = 1; off < 32; off <<= 1) {
            float tmp = __shfl_down_sync(0xffffffffu, q, off);
            if (lane + off < 32) q += tmp;
        }
        float pex = __shfl_up_sync(0xffffffffu, p, 1);
        if (lane == 0) pex = 0.0f;
        float sex = __shfl_down_sync(0xffffffffu, q, 1);
        if (lane == 31) sex = 0.0f;
        if (lane == 31) wtot[w] = p;
        __syncthreads();

        float offp = 0.0f, offs = 0.0f, total = 0.0f;
        #pragma unroll
        for (int ww = 0; ww < 8; ww++) {
            float tw = wtot[ww];
            total += tw;
            if (ww < w) offp += tw;
            if (ww > w) offs += tw;
        }
        const float bp = offp + pex;
        const float bs = offs + sex;
        sm.loss.psX[2 * tid + 1] = bp + v0;
        sm.loss.psX[2 * tid + 2] = bp + v0 + v1;
        sm.loss.ssX[2 * tid]     = bs + v1 + v0;
        sm.loss.ssX[2 * tid + 1] = bs + v1;
        if (tid == 0) { sm.loss.psX[0] = 0.0f; sm.loss.ssX[N2] = 0.0f; }
        __syncthreads();

        const int ri = ri_sh;
        const float* ts  = sm.loss.ts;
        const float* psX = sm.loss.psX;
        const float* ssX = sm.loss.ssX;

        // uniform branchless denom: L = #{m: ti-ts[m] >= ak}, R = first{m: ts[m]-ti >= ak}
        const int r1 = tid, r2 = tid + 256;
        const float ak1 = fabsf(ti - ts[r1]);
        const float ak2 = fabsf(ti - ts[r2]);
        int L1 = 0, L2 = 0, R1 = 0, R2 = 0;
        #pragma unroll
        for (int step = 256; step > 0; step >>= 1) {
            if (ti - ts[L1 + step - 1] >= ak1) L1 += step;
            if (ti - ts[L2 + step - 1] >= ak2) L2 += step;
            if (ts[R1 + step - 1] - ti <  ak1) R1 += step;
            if (ts[R2 + step - 1] - ti <  ak2) R2 += step;
        }
        // steps sum to 511; R may legitimately be 512 -> one extra probe.
        if (ts[R1] - ti < ak1) R1++;
        if (ts[R2] - ti < ak2) R2++;
        float den1 = psX[L1] + ssX[R1];
        float den2 = psX[L2] + ssX[R2];
        if (ak1 == 0.0f) den1 = total - 1.0f;
        if (ak2 == 0.0f) den2 = total - 1.0f;
        float local = 0.0f;
        if (r1 != ri) local += sm.loss.ds[r1] + __logf(den1);
        if (r2 != ri) local += sm.loss.ds[r2] + __logf(den2);

        #pragma unroll
        for (int o = 16; o > 0; o >>= 1)
            local += __shfl_xor_sync(0xffffffffu, local, o);
        if (lane == 0) red[w] = local;
        __syncthreads();
        if (tid == 0) {
            float sum = 0.0f;
            #pragma unroll
            for (int k = 0; k < 8; k++) sum += red[k];
            g_part[bid] = sum;
        }
    }

    // ============ BARRIER 2 (arrival-only) + PHASE C ============
    __syncthreads();
    if (tid == 0) {
        __threadfence();
        atomicAdd(&g_count2, 1u);
    }
    if (bid != 0) return;

    if (tid == 0) {
        while (*((volatile unsigned*)&g_count2) != NBLK) { __nanosleep(64); }
        g_count2 = 0;   // reset for next graph replay
        g_sense  = 0;   // reset barrier-1 sense
        __threadfence();
    }
    __syncthreads();

    {
        float v = g_part[tid] + g_part[tid + 256];
        #pragma unroll
        for (int o = 16; o > 0; o >>= 1)
            v += __shfl_xor_sync(0xffffffffu, v, o);
        if (lane == 0) red[w] = v;
        __syncthreads();
        if (tid == 0) {
            float sum = 0.0f;
            #pragma unroll
            for (int k = 0; k < 8; k++) sum += red[k];
            const float scale = 1.0f / (float(N2) * float(N2 - 1));
            *out = sum * scale;
        }
    }
}

extern "C" void kernel_launch(void* const* d_in, const int* in_sizes, int n_in,
                              void* d_out, int out_size) {
    const float* E = (const float*)d_in[0];   // embeddings [512,256]
    const float* T = (const float*)d_in[1];   // targets    [512]
    float* out = (float*)d_out;

    fused_kernel<<<NBLK, 256>>>(E, T, out);
}